// round 2
// baseline (speedup 1.0000x reference)
#include <cuda_runtime.h>
#include <cuda_bf16.h>

// Problem dims (fixed by the dataset)
#define D_     2048
#define K_     2048
#define NTOT   (3 * D_)        // 6144
#define M_     8192            // 4 * 2048
#define R_     8

// 50.3 MB static scratch for the patched weight (allocation-free rule)
__device__ float g_Wmod[(size_t)NTOT * K_];

// ---------------------------------------------------------------------------
// Kernel 1: Wmod = W + [0 ; B1@A1 ; B2@A2]   (rank-8 outer products)
// One thread per 4 consecutive k's of one output row n.
// ---------------------------------------------------------------------------
__global__ void build_wmod(const float* __restrict__ W,
                           const float* __restrict__ A1,
                           const float* __restrict__ B1,
                           const float* __restrict__ A2,
                           const float* __restrict__ B2) {
    int idx = blockIdx.x * blockDim.x + threadIdx.x;        // float4 index
    if (idx >= NTOT * (K_ / 4)) return;
    int n  = idx / (K_ / 4);
    int k4 = (idx % (K_ / 4)) * 4;

    float4 w = *(const float4*)(W + (size_t)n * K_ + k4);

    if (n >= D_) {
        const float* A;
        const float* Brow;
        if (n < 2 * D_) { A = A1; Brow = B1 + (size_t)(n - D_)     * R_; }
        else            { A = A2; Brow = B2 + (size_t)(n - 2 * D_) * R_; }
#pragma unroll
        for (int r = 0; r < R_; r++) {
            float bv = Brow[r];
            const float* Ar = A + (size_t)r * K_ + k4;
            w.x = fmaf(bv, Ar[0], w.x);
            w.y = fmaf(bv, Ar[1], w.y);
            w.z = fmaf(bv, Ar[2], w.z);
            w.w = fmaf(bv, Ar[3], w.w);
        }
    }
    *(float4*)(g_Wmod + (size_t)n * K_ + k4) = w;
}

// ---------------------------------------------------------------------------
// Kernel 2: out[M,N] = X[M,K] @ Wmod[N,K]^T + bias[N]
// Classic SGEMM: 128x128 block tile, BK=16, 256 threads, 8x8 per thread.
// ---------------------------------------------------------------------------
#define BM 128
#define BN 128
#define BK 16
#define TM 8
#define TN 8
#define PAD 4   // smem row pad (keeps 16B alignment for float4 smem loads)

__global__ __launch_bounds__(256, 2)
void sgemm_bias(const float* __restrict__ X,
                const float* __restrict__ bias,
                float*       __restrict__ out) {
    __shared__ __align__(16) float Xs[BK][BM + PAD];
    __shared__ __align__(16) float Ws[BK][BN + PAD];

    const int tid = threadIdx.x;
    const int bm  = blockIdx.y * BM;
    const int bn  = blockIdx.x * BN;
    const int ty  = tid >> 4;          // 0..15  -> m micro-tile
    const int tx  = tid & 15;          // 0..15  -> n micro-tile

    float acc[TM][TN];
#pragma unroll
    for (int i = 0; i < TM; i++)
#pragma unroll
        for (int j = 0; j < TN; j++) acc[i][j] = 0.0f;

    const float* Wm = g_Wmod;

    for (int k0 = 0; k0 < K_; k0 += BK) {
        // Stage tiles: 128 rows x 16 k's each for X and W. 512 float4 per
        // tensor, 256 threads -> 2 float4 each, stored transposed [k][row].
#pragma unroll
        for (int l = 0; l < 2; l++) {
            int f   = tid + l * 256;
            int row = f >> 2;            // 0..127
            int kc  = (f & 3) << 2;      // 0,4,8,12

            float4 v = *(const float4*)(X + (size_t)(bm + row) * K_ + k0 + kc);
            Xs[kc + 0][row] = v.x;
            Xs[kc + 1][row] = v.y;
            Xs[kc + 2][row] = v.z;
            Xs[kc + 3][row] = v.w;

            float4 w = *(const float4*)(Wm + (size_t)(bn + row) * K_ + k0 + kc);
            Ws[kc + 0][row] = w.x;
            Ws[kc + 1][row] = w.y;
            Ws[kc + 2][row] = w.z;
            Ws[kc + 3][row] = w.w;
        }
        __syncthreads();

#pragma unroll
        for (int kk = 0; kk < BK; kk++) {
            float xr[TM], wr[TN];
            float4 a0 = *(const float4*)&Xs[kk][ty * TM + 0];
            float4 a1 = *(const float4*)&Xs[kk][ty * TM + 4];
            float4 b0 = *(const float4*)&Ws[kk][tx * TN + 0];
            float4 b1 = *(const float4*)&Ws[kk][tx * TN + 4];
            xr[0]=a0.x; xr[1]=a0.y; xr[2]=a0.z; xr[3]=a0.w;
            xr[4]=a1.x; xr[5]=a1.y; xr[6]=a1.z; xr[7]=a1.w;
            wr[0]=b0.x; wr[1]=b0.y; wr[2]=b0.z; wr[3]=b0.w;
            wr[4]=b1.x; wr[5]=b1.y; wr[6]=b1.z; wr[7]=b1.w;
#pragma unroll
            for (int i = 0; i < TM; i++)
#pragma unroll
                for (int j = 0; j < TN; j++)
                    acc[i][j] = fmaf(xr[i], wr[j], acc[i][j]);
        }
        __syncthreads();
    }

    // Epilogue: add bias, vectorized stores.
    float4 bz0 = *(const float4*)(bias + bn + tx * TN + 0);
    float4 bz1 = *(const float4*)(bias + bn + tx * TN + 4);
#pragma unroll
    for (int i = 0; i < TM; i++) {
        size_t o = (size_t)(bm + ty * TM + i) * NTOT + bn + tx * TN;
        float4 r0 = make_float4(acc[i][0] + bz0.x, acc[i][1] + bz0.y,
                                acc[i][2] + bz0.z, acc[i][3] + bz0.w);
        float4 r1 = make_float4(acc[i][4] + bz1.x, acc[i][5] + bz1.y,
                                acc[i][6] + bz1.z, acc[i][7] + bz1.w);
        *(float4*)(out + o + 0) = r0;
        *(float4*)(out + o + 4) = r1;
    }
}

// ---------------------------------------------------------------------------
extern "C" void kernel_launch(void* const* d_in, const int* in_sizes, int n_in,
                              void* d_out, int out_size) {
    const float* x  = (const float*)d_in[0];
    const float* W  = (const float*)d_in[1];
    const float* b  = (const float*)d_in[2];
    const float* A1 = (const float*)d_in[3];
    const float* B1 = (const float*)d_in[4];
    const float* A2 = (const float*)d_in[5];
    const float* B2 = (const float*)d_in[6];
    float* out = (float*)d_out;

    // 1) patch the fused weight with the two rank-8 LoRA deltas
    {
        int total = NTOT * (K_ / 4);
        build_wmod<<<(total + 255) / 256, 256>>>(W, A1, B1, A2, B2);
    }
    // 2) big GEMM + bias
    {
        dim3 grid(NTOT / BN, M_ / BM);   // (48, 64)
        sgemm_bias<<<grid, 256>>>(x, b, out);
    }
}

// round 4
// speedup vs baseline: 2.9670x; 2.9670x over previous
#include <cuda_runtime.h>
#include <cuda_bf16.h>
#include <cstdint>

// ---------------------------------------------------------------------------
// Problem dims (fixed by the dataset)
// ---------------------------------------------------------------------------
#define D_     2048
#define K_     2048
#define NTOT   6144            // 3*D
#define M_     8192            // 4*2048
#define R_     8

#define KC        64           // k-elems per chunk (128B bf16 rows, SW128)
#define NKC       32           // K_/KC
#define MHALVES   64           // M_/128
#define NHALVES   48           // NTOT/128
#define CHUNK_BYTES 32768      // one (hi,lo) 128x64 bf16 tile pair
#define STAGE_BYTES 65536      // A chunk (32K) + B chunk (32K)
#define SMEM_REQ  (2 * STAGE_BYTES + 1024)

// Pre-split bf16 blobs, stored as byte-exact SW128 tile images:
// blob[half*32 + kc] = 32KB { hi 128x64 tile 16KB, lo tile 16KB }
// byte (r, c) of a tile at sw128(r*128 + c*2)
__device__ __align__(128) unsigned char g_X[(size_t)MHALVES * NKC * CHUNK_BYTES]; // 64 MB
__device__ __align__(128) unsigned char g_W[(size_t)NHALVES * NKC * CHUNK_BYTES]; // 48 MB

// ---------------------------------------------------------------------------
// PTX helpers (all baseline sm_80/90 — no "a" features)
// ---------------------------------------------------------------------------
__device__ __forceinline__ uint32_t smem_u32(const void* p) {
    uint32_t a;
    asm("{ .reg .u64 t; cvta.to.shared.u64 t, %1; cvt.u32.u64 %0, t; }" : "=r"(a) : "l"(p));
    return a;
}
#define CP_ASYNC16(s, g) \
    asm volatile("cp.async.cg.shared.global [%0], [%1], 16;" :: "r"(s), "l"(g) : "memory")
#define CP_COMMIT() asm volatile("cp.async.commit_group;" ::: "memory")
#define CP_WAIT(n)  asm volatile("cp.async.wait_group %0;" :: "n"(n) : "memory")

#define LDSM_X4(r0, r1, r2, r3, a) \
    asm volatile("ldmatrix.sync.aligned.m8n8.x4.shared.b16 {%0,%1,%2,%3}, [%4];" \
                 : "=r"(r0), "=r"(r1), "=r"(r2), "=r"(r3) : "r"(a))
#define LDSM_X2(r0, r1, a) \
    asm volatile("ldmatrix.sync.aligned.m8n8.x2.shared.b16 {%0,%1}, [%2];" \
                 : "=r"(r0), "=r"(r1) : "r"(a))

#define MMA_BF16(d, a, b) \
    asm volatile("mma.sync.aligned.m16n8k16.row.col.f32.bf16.bf16.f32 " \
                 "{%0,%1,%2,%3}, {%4,%5,%6,%7}, {%8,%9}, {%0,%1,%2,%3};" \
                 : "+f"((d)[0]), "+f"((d)[1]), "+f"((d)[2]), "+f"((d)[3]) \
                 : "r"((a)[0]), "r"((a)[1]), "r"((a)[2]), "r"((a)[3]), \
                   "r"((b)[0]), "r"((b)[1]))

__device__ __forceinline__ uint32_t swz(uint32_t off) { return off ^ ((off >> 3) & 0x70u); }

// ---------------------------------------------------------------------------
// Split-convert kernels: fp32 -> (hi, lo) bf16 in pre-swizzled blob layout
// ---------------------------------------------------------------------------
__device__ __forceinline__ void split8_store(const float* xs, unsigned char* blobbase,
                                             unsigned m_in_half, unsigned k_in_chunk) {
    union { unsigned short s[8]; uint4 v; } hi, lo;
#pragma unroll
    for (int j = 0; j < 8; j++) {
        float x = xs[j];
        __nv_bfloat16 h = __float2bfloat16(x);
        hi.s[j] = __bfloat16_as_ushort(h);
        lo.s[j] = __bfloat16_as_ushort(__float2bfloat16(x - __bfloat162float(h)));
    }
    unsigned off = (m_in_half << 7) | (k_in_chunk << 1);
    unsigned sw  = swz(off);
    *(uint4*)(blobbase + sw)         = hi.v;
    *(uint4*)(blobbase + 16384 + sw) = lo.v;
}

__global__ void __launch_bounds__(256) convX(const float* __restrict__ X) {
    unsigned idx = blockIdx.x * 256u + threadIdx.x;
    unsigned m  = idx >> 8;
    unsigned k0 = (idx & 255u) << 3;
    const float4* src = (const float4*)(X + (size_t)m * K_ + k0);
    float4 v0 = src[0], v1 = src[1];
    float xs[8] = {v0.x, v0.y, v0.z, v0.w, v1.x, v1.y, v1.z, v1.w};
    size_t blob = ((size_t)(m >> 7) * NKC + (k0 >> 6)) * CHUNK_BYTES;
    split8_store(xs, g_X + blob, m & 127u, k0 & 63u);
}

__global__ void __launch_bounds__(256) convW(const float* __restrict__ W,
                                             const float* __restrict__ A1,
                                             const float* __restrict__ B1,
                                             const float* __restrict__ A2,
                                             const float* __restrict__ B2) {
    unsigned idx = blockIdx.x * 256u + threadIdx.x;
    unsigned n  = idx >> 8;
    unsigned k0 = (idx & 255u) << 3;
    const float4* src = (const float4*)(W + (size_t)n * K_ + k0);
    float4 v0 = src[0], v1 = src[1];
    float xs[8] = {v0.x, v0.y, v0.z, v0.w, v1.x, v1.y, v1.z, v1.w};
    if (n >= D_) {
        const float* A;
        const float* Brow;
        if (n < 2 * D_) { A = A1; Brow = B1 + (size_t)(n - D_) * R_; }
        else            { A = A2; Brow = B2 + (size_t)(n - 2 * D_) * R_; }
#pragma unroll
        for (int r = 0; r < R_; r++) {
            float bv = Brow[r];
            const float* Ar = A + (size_t)r * K_ + k0;
#pragma unroll
            for (int j = 0; j < 8; j++) xs[j] = fmaf(bv, Ar[j], xs[j]);
        }
    }
    size_t blob = ((size_t)(n >> 7) * NKC + (k0 >> 6)) * CHUNK_BYTES;
    split8_store(xs, g_W + blob, n & 127u, k0 & 63u);
}

// ---------------------------------------------------------------------------
// GEMM: 128x128 CTA tile, 8 warps (2m x 4n, 64x32 each), BK=64, 2-stage
// cp.async pipeline, mma.sync bf16 HMMA, split 3-pass for fp32 accuracy.
// ---------------------------------------------------------------------------
__device__ __forceinline__ void issue_chunk(uint32_t st, const unsigned char* ga,
                                            const unsigned char* gb, int tid) {
#pragma unroll
    for (int i = 0; i < 8; i++) {
        uint32_t off = (uint32_t)(i * 256 + tid) * 16u;
        CP_ASYNC16(st + off,          ga + off);
        CP_ASYNC16(st + 32768u + off, gb + off);
    }
}

__global__ void __launch_bounds__(256, 1)
gemm_hmma(const float* __restrict__ bias, float* __restrict__ out) {
    extern __shared__ __align__(16) unsigned char smem_raw[];
    const uint32_t base = (smem_u32(smem_raw) + 1023u) & ~1023u;

    const int tid  = threadIdx.x;
    const int wid  = tid >> 5;
    const int lane = tid & 31;
    const int wm   = wid >> 2;          // 0..1  (64-row slab)
    const int wn   = wid & 3;           // 0..3  (32-col slab)

    const int bn = blockIdx.x;          // 0..47
    const int bm = blockIdx.y;          // 0..63

    const unsigned char* Ab = g_X + (size_t)bm * NKC * CHUNK_BYTES;
    const unsigned char* Bb = g_W + (size_t)bn * NKC * CHUNK_BYTES;

    // Per-lane ldmatrix address bases (pre-swizzle byte offsets within a tile)
    const uint32_t a_base = (uint32_t)((wm * 64 + (lane & 15)) * 128 + ((lane >> 4) & 1) * 16);
    const uint32_t b_base = (uint32_t)((wn * 32 + (lane & 7)) * 128 + ((lane >> 3) & 1) * 16);

    float acc[4][4][4];
#pragma unroll
    for (int i = 0; i < 4; i++)
#pragma unroll
        for (int j = 0; j < 4; j++)
#pragma unroll
            for (int q = 0; q < 4; q++) acc[i][j][q] = 0.0f;

    issue_chunk(base, Ab, Bb, tid);
    CP_COMMIT();

    for (int kc = 0; kc < NKC; kc++) {
        if (kc + 1 < NKC) {
            issue_chunk(base + (uint32_t)((kc + 1) & 1) * STAGE_BYTES,
                        Ab + (size_t)(kc + 1) * CHUNK_BYTES,
                        Bb + (size_t)(kc + 1) * CHUNK_BYTES, tid);
            CP_COMMIT();
            CP_WAIT(1);
        } else {
            CP_WAIT(0);
        }
        __syncthreads();

        const uint32_t st  = base + (uint32_t)(kc & 1) * STAGE_BYTES;
        const uint32_t Ahi = st;
        const uint32_t Alo = st + 16384u;
        const uint32_t Bhi = st + 32768u;
        const uint32_t Blo = st + 49152u;

#pragma unroll
        for (int kk = 0; kk < 4; kk++) {
            const uint32_t kb = (uint32_t)kk * 32u;
            uint32_t ah[16], al[16], bh[8], bl[8];
#pragma unroll
            for (int i = 0; i < 4; i++) {
                uint32_t o = swz(a_base + (uint32_t)i * 2048u + kb);
                LDSM_X4(ah[4*i+0], ah[4*i+1], ah[4*i+2], ah[4*i+3], Ahi + o);
                LDSM_X4(al[4*i+0], al[4*i+1], al[4*i+2], al[4*i+3], Alo + o);
            }
#pragma unroll
            for (int j = 0; j < 4; j++) {
                uint32_t o = swz(b_base + (uint32_t)j * 1024u + kb);
                LDSM_X2(bh[2*j+0], bh[2*j+1], Bhi + o);
                LDSM_X2(bl[2*j+0], bl[2*j+1], Blo + o);
            }
#pragma unroll
            for (int i = 0; i < 4; i++)
#pragma unroll
                for (int j = 0; j < 4; j++) MMA_BF16(acc[i][j], &ah[4*i], &bh[2*j]);
#pragma unroll
            for (int i = 0; i < 4; i++)
#pragma unroll
                for (int j = 0; j < 4; j++) MMA_BF16(acc[i][j], &ah[4*i], &bl[2*j]);
#pragma unroll
            for (int i = 0; i < 4; i++)
#pragma unroll
                for (int j = 0; j < 4; j++) MMA_BF16(acc[i][j], &al[4*i], &bh[2*j]);
        }
        __syncthreads();
    }

    // ---- epilogue: bias + store ----
    const int m0 = bm * 128 + wm * 64;
    const int n0 = bn * 128 + wn * 32;
    const int r  = lane >> 2;
    const int cp = (lane & 3) * 2;

#pragma unroll
    for (int j = 0; j < 4; j++) {
        const int n = n0 + j * 8 + cp;
        const float2 bv = *(const float2*)(bias + n);
#pragma unroll
        for (int i = 0; i < 4; i++) {
            const int row0 = m0 + i * 16 + r;
            float2 o0 = make_float2(acc[i][j][0] + bv.x, acc[i][j][1] + bv.y);
            float2 o1 = make_float2(acc[i][j][2] + bv.x, acc[i][j][3] + bv.y);
            *(float2*)(out + (size_t)row0 * NTOT + n)       = o0;
            *(float2*)(out + (size_t)(row0 + 8) * NTOT + n) = o1;
        }
    }
}

// ---------------------------------------------------------------------------
extern "C" void kernel_launch(void* const* d_in, const int* in_sizes, int n_in,
                              void* d_out, int out_size) {
    const float* x  = (const float*)d_in[0];
    const float* W  = (const float*)d_in[1];
    const float* b  = (const float*)d_in[2];
    const float* A1 = (const float*)d_in[3];
    const float* B1 = (const float*)d_in[4];
    const float* A2 = (const float*)d_in[5];
    const float* B2 = (const float*)d_in[6];
    float* out = (float*)d_out;

    convX<<<M_ * (K_ / 8) / 256, 256>>>(x);
    convW<<<NTOT * (K_ / 8) / 256, 256>>>(W, A1, B1, A2, B2);

    cudaFuncSetAttribute(gemm_hmma, cudaFuncAttributeMaxDynamicSharedMemorySize, SMEM_REQ);
    dim3 grid(NTOT / 128, M_ / 128);   // (48, 64)
    gemm_hmma<<<grid, 256, SMEM_REQ>>>(b, out);
}

// round 5
// speedup vs baseline: 6.3537x; 2.1415x over previous
#include <cuda_runtime.h>
#include <cuda_bf16.h>
#include <cuda_fp16.h>
#include <cstdint>

// ---------------------------------------------------------------------------
// Problem dims (fixed by the dataset)
// ---------------------------------------------------------------------------
#define D_     2048
#define K_     2048
#define NTOT   6144            // 3*D
#define M_     8192            // 4*2048
#define R_     8

#define KC        64           // k-elems per chunk (128B fp16 rows, SW128)
#define NKC       32           // K_/KC
#define MHALVES   64           // M_/128
#define NHALVES   48           // NTOT/128
#define CHUNK_BYTES 16384      // one 128x64 fp16 tile (SW128 image)
#define STAGES    5
#define STAGE_BYTES 32768      // A chunk (16K) + B chunk (16K)
#define SMEM_REQ  (STAGES * STAGE_BYTES + 1024)

// fp16 blobs, stored as byte-exact SW128 tile images:
// blob[half*32 + kc] = 16KB tile; byte (r, c) at sw128(r*128 + c*2)
__device__ __align__(128) unsigned char g_X[(size_t)MHALVES * NKC * CHUNK_BYTES]; // 32 MB
__device__ __align__(128) unsigned char g_W[(size_t)NHALVES * NKC * CHUNK_BYTES]; // 24 MB

// ---------------------------------------------------------------------------
// PTX helpers (baseline sm_80/90 features only — no "a" suffix features)
// ---------------------------------------------------------------------------
__device__ __forceinline__ uint32_t smem_u32(const void* p) {
    uint32_t a;
    asm("{ .reg .u64 t; cvta.to.shared.u64 t, %1; cvt.u32.u64 %0, t; }" : "=r"(a) : "l"(p));
    return a;
}
#define CP_ASYNC16(s, g) \
    asm volatile("cp.async.cg.shared.global [%0], [%1], 16;" :: "r"(s), "l"(g) : "memory")
#define CP_COMMIT() asm volatile("cp.async.commit_group;" ::: "memory")
#define CP_WAIT(n)  asm volatile("cp.async.wait_group %0;" :: "n"(n) : "memory")

#define LDSM_X4(r0, r1, r2, r3, a) \
    asm volatile("ldmatrix.sync.aligned.m8n8.x4.shared.b16 {%0,%1,%2,%3}, [%4];" \
                 : "=r"(r0), "=r"(r1), "=r"(r2), "=r"(r3) : "r"(a))

#define MMA_F16(d, a0, a1, a2, a3, b0, b1) \
    asm volatile("mma.sync.aligned.m16n8k16.row.col.f32.f16.f16.f32 " \
                 "{%0,%1,%2,%3}, {%4,%5,%6,%7}, {%8,%9}, {%0,%1,%2,%3};" \
                 : "+f"((d)[0]), "+f"((d)[1]), "+f"((d)[2]), "+f"((d)[3]) \
                 : "r"(a0), "r"(a1), "r"(a2), "r"(a3), "r"(b0), "r"(b1))

__device__ __forceinline__ uint32_t swz(uint32_t off) { return off ^ ((off >> 3) & 0x70u); }

// ---------------------------------------------------------------------------
// Convert kernels: fp32 -> fp16 in pre-swizzled blob layout
// ---------------------------------------------------------------------------
__device__ __forceinline__ void cvt8_store(const float* xs, unsigned char* blobbase,
                                           unsigned m_in_half, unsigned k_in_chunk) {
    union { unsigned short s[8]; uint4 v; } h;
#pragma unroll
    for (int j = 0; j < 8; j++) h.s[j] = __half_as_ushort(__float2half_rn(xs[j]));
    unsigned off = (m_in_half << 7) | (k_in_chunk << 1);
    *(uint4*)(blobbase + swz(off)) = h.v;
}

__global__ void __launch_bounds__(256) convX(const float* __restrict__ X) {
    unsigned idx = blockIdx.x * 256u + threadIdx.x;
    unsigned m  = idx >> 8;
    unsigned k0 = (idx & 255u) << 3;
    const float4* src = (const float4*)(X + (size_t)m * K_ + k0);
    float4 v0 = src[0], v1 = src[1];
    float xs[8] = {v0.x, v0.y, v0.z, v0.w, v1.x, v1.y, v1.z, v1.w};
    size_t blob = ((size_t)(m >> 7) * NKC + (k0 >> 6)) * CHUNK_BYTES;
    cvt8_store(xs, g_X + blob, m & 127u, k0 & 63u);
}

__global__ void __launch_bounds__(256) convW(const float* __restrict__ W,
                                             const float* __restrict__ A1,
                                             const float* __restrict__ B1,
                                             const float* __restrict__ A2,
                                             const float* __restrict__ B2) {
    unsigned idx = blockIdx.x * 256u + threadIdx.x;
    unsigned n  = idx >> 8;
    unsigned k0 = (idx & 255u) << 3;
    const float4* src = (const float4*)(W + (size_t)n * K_ + k0);
    float4 v0 = src[0], v1 = src[1];
    float xs[8] = {v0.x, v0.y, v0.z, v0.w, v1.x, v1.y, v1.z, v1.w};
    if (n >= D_) {
        const float* A;
        const float* Brow;
        if (n < 2 * D_) { A = A1; Brow = B1 + (size_t)(n - D_) * R_; }
        else            { A = A2; Brow = B2 + (size_t)(n - 2 * D_) * R_; }
#pragma unroll
        for (int r = 0; r < R_; r++) {
            float bv = Brow[r];
            const float* Ar = A + (size_t)r * K_ + k0;
#pragma unroll
            for (int j = 0; j < 8; j++) xs[j] = fmaf(bv, Ar[j], xs[j]);
        }
    }
    size_t blob = ((size_t)(n >> 7) * NKC + (k0 >> 6)) * CHUNK_BYTES;
    cvt8_store(xs, g_W + blob, n & 127u, k0 & 63u);
}

// ---------------------------------------------------------------------------
// GEMM: 128x128 CTA tile, 8 warps (2m x 4n, 64x32 each), BK=64,
// 5-stage cp.async pipeline (one __syncthreads per chunk), fp16 HMMA.
// ---------------------------------------------------------------------------
__device__ __forceinline__ void issue_chunk(uint32_t st, const unsigned char* ga,
                                            const unsigned char* gb, int tid) {
#pragma unroll
    for (int i = 0; i < 4; i++) {
        uint32_t off = (uint32_t)(i * 256 + tid) * 16u;
        CP_ASYNC16(st + off,          ga + off);
        CP_ASYNC16(st + 16384u + off, gb + off);
    }
}

__global__ void __launch_bounds__(256, 1)
gemm_hmma(const float* __restrict__ bias, float* __restrict__ out) {
    extern __shared__ __align__(16) unsigned char smem_raw[];
    const uint32_t base = (smem_u32(smem_raw) + 1023u) & ~1023u;

    const int tid  = threadIdx.x;
    const int wid  = tid >> 5;
    const int lane = tid & 31;
    const int wm   = wid >> 2;          // 0..1  (64-row slab)
    const int wn   = wid & 3;           // 0..3  (32-col slab)

    const int bn = blockIdx.x;          // 0..47
    const int bm = blockIdx.y;          // 0..63

    const unsigned char* Ab = g_X + (size_t)bm * NKC * CHUNK_BYTES;
    const unsigned char* Bb = g_W + (size_t)bn * NKC * CHUNK_BYTES;

    // Per-lane ldmatrix base byte offsets (pre-swizzle) within a tile image.
    // A (x4): lanes 0-15 rows, lanes 16-31 rows at +16B k-offset.
    const uint32_t a_base = (uint32_t)((wm * 64 + (lane & 15)) * 128 + ((lane >> 4) & 1) * 16);
    // B (x4): mats = {n0-7 k0, n0-7 k1, n8-15 k0, n8-15 k1}
    const uint32_t b_base = (uint32_t)((wn * 32 + (lane & 7) + ((lane >> 4) << 3)) * 128
                                       + ((lane >> 3) & 1) * 16);

    float acc[4][4][4];
#pragma unroll
    for (int i = 0; i < 4; i++)
#pragma unroll
        for (int j = 0; j < 4; j++)
#pragma unroll
            for (int q = 0; q < 4; q++) acc[i][j][q] = 0.0f;

    // Prologue: fill STAGES-1 stages
#pragma unroll
    for (int s = 0; s < STAGES - 1; s++) {
        issue_chunk(base + (uint32_t)s * STAGE_BYTES,
                    Ab + (size_t)s * CHUNK_BYTES,
                    Bb + (size_t)s * CHUNK_BYTES, tid);
        CP_COMMIT();
    }

    for (int kc = 0; kc < NKC; kc++) {
        CP_WAIT(STAGES - 2);            // chunk kc resident
        __syncthreads();                // all warps done reading stage (kc-1)%STAGES

        if (kc + STAGES - 1 < NKC) {
            issue_chunk(base + (uint32_t)((kc + STAGES - 1) % STAGES) * STAGE_BYTES,
                        Ab + (size_t)(kc + STAGES - 1) * CHUNK_BYTES,
                        Bb + (size_t)(kc + STAGES - 1) * CHUNK_BYTES, tid);
        }
        CP_COMMIT();                    // keep group count uniform

        const uint32_t st = base + (uint32_t)(kc % STAGES) * STAGE_BYTES;
        const uint32_t As = st;
        const uint32_t Bs = st + 16384u;

#pragma unroll
        for (int kk = 0; kk < 4; kk++) {
            const uint32_t kb = (uint32_t)kk * 32u;
            uint32_t a[16], b[8];
#pragma unroll
            for (int i = 0; i < 4; i++) {
                uint32_t o = swz(a_base + (uint32_t)i * 2048u + kb);
                LDSM_X4(a[4*i+0], a[4*i+1], a[4*i+2], a[4*i+3], As + o);
            }
#pragma unroll
            for (int g = 0; g < 2; g++) {
                uint32_t o = swz(b_base + (uint32_t)g * 2048u + kb);
                LDSM_X4(b[4*g+0], b[4*g+1], b[4*g+2], b[4*g+3], Bs + o);
            }
#pragma unroll
            for (int i = 0; i < 4; i++) {
#pragma unroll
                for (int j = 0; j < 4; j++) {
                    const int g = j >> 1, h = (j & 1) << 1;
                    MMA_F16(acc[i][j], a[4*i+0], a[4*i+1], a[4*i+2], a[4*i+3],
                            b[4*g+h], b[4*g+h+1]);
                }
            }
        }
    }

    // ---- epilogue: bias + store ----
    const int m0 = bm * 128 + wm * 64;
    const int n0 = bn * 128 + wn * 32;
    const int r  = lane >> 2;
    const int cp = (lane & 3) * 2;

#pragma unroll
    for (int j = 0; j < 4; j++) {
        const int n = n0 + j * 8 + cp;
        const float2 bv = *(const float2*)(bias + n);
#pragma unroll
        for (int i = 0; i < 4; i++) {
            const int row0 = m0 + i * 16 + r;
            float2 o0 = make_float2(acc[i][j][0] + bv.x, acc[i][j][1] + bv.y);
            float2 o1 = make_float2(acc[i][j][2] + bv.x, acc[i][j][3] + bv.y);
            *(float2*)(out + (size_t)row0 * NTOT + n)       = o0;
            *(float2*)(out + (size_t)(row0 + 8) * NTOT + n) = o1;
        }
    }
}

// ---------------------------------------------------------------------------
extern "C" void kernel_launch(void* const* d_in, const int* in_sizes, int n_in,
                              void* d_out, int out_size) {
    const float* x  = (const float*)d_in[0];
    const float* W  = (const float*)d_in[1];
    const float* b  = (const float*)d_in[2];
    const float* A1 = (const float*)d_in[3];
    const float* B1 = (const float*)d_in[4];
    const float* A2 = (const float*)d_in[5];
    const float* B2 = (const float*)d_in[6];
    float* out = (float*)d_out;

    convX<<<M_ * (K_ / 8) / 256, 256>>>(x);
    convW<<<NTOT * (K_ / 8) / 256, 256>>>(W, A1, B1, A2, B2);

    cudaFuncSetAttribute(gemm_hmma, cudaFuncAttributeMaxDynamicSharedMemorySize, SMEM_REQ);
    dim3 grid(NTOT / 128, M_ / 128);   // (48, 64)
    gemm_hmma<<<grid, 256, SMEM_REQ>>>(b, out);
}

// round 6
// speedup vs baseline: 6.8970x; 1.0855x over previous
#include <cuda_runtime.h>
#include <cuda_bf16.h>
#include <cuda_fp16.h>
#include <cstdint>

// ---------------------------------------------------------------------------
// Problem dims (fixed by the dataset)
// ---------------------------------------------------------------------------
#define D_     2048
#define K_     2048
#define NTOT   6144            // 3*D
#define M_     8192            // 4*2048
#define R_     8

#define KC        64           // k-elems per chunk (128B fp16 rows, SW128)
#define NKC       32           // K_/KC
#define MHALVES   64           // M_/128
#define NHALVES   48           // NTOT/128
#define TILE_BYTES  16384      // one 128x64 fp16 tile (SW128 image)
#define STAGES    4
#define STAGE_BYTES 49152      // A (16K) + B two halves (32K)
#define SMEM_REQ  (STAGES * STAGE_BYTES + 1024)

// fp16 blobs, stored as byte-exact SW128 tile images:
// blob[half*32 + kc] = 16KB tile; byte (r, c) at sw128(r*128 + c*2)
__device__ __align__(128) unsigned char g_X[(size_t)MHALVES * NKC * TILE_BYTES]; // 32 MB
__device__ __align__(128) unsigned char g_W[(size_t)NHALVES * NKC * TILE_BYTES]; // 24 MB

// ---------------------------------------------------------------------------
// PTX helpers (baseline sm_80/90 features only)
// ---------------------------------------------------------------------------
__device__ __forceinline__ uint32_t smem_u32(const void* p) {
    uint32_t a;
    asm("{ .reg .u64 t; cvta.to.shared.u64 t, %1; cvt.u32.u64 %0, t; }" : "=r"(a) : "l"(p));
    return a;
}
#define CP_ASYNC16(s, g) \
    asm volatile("cp.async.cg.shared.global [%0], [%1], 16;" :: "r"(s), "l"(g) : "memory")
#define CP_COMMIT() asm volatile("cp.async.commit_group;" ::: "memory")
#define CP_WAIT(n)  asm volatile("cp.async.wait_group %0;" :: "n"(n) : "memory")

#define LDSM_X4(r0, r1, r2, r3, a) \
    asm volatile("ldmatrix.sync.aligned.m8n8.x4.shared.b16 {%0,%1,%2,%3}, [%4];" \
                 : "=r"(r0), "=r"(r1), "=r"(r2), "=r"(r3) : "r"(a))

#define MMA_F16(d, a0, a1, a2, a3, b0, b1) \
    asm volatile("mma.sync.aligned.m16n8k16.row.col.f32.f16.f16.f32 " \
                 "{%0,%1,%2,%3}, {%4,%5,%6,%7}, {%8,%9}, {%0,%1,%2,%3};" \
                 : "+f"((d)[0]), "+f"((d)[1]), "+f"((d)[2]), "+f"((d)[3]) \
                 : "r"(a0), "r"(a1), "r"(a2), "r"(a3), "r"(b0), "r"(b1))

__device__ __forceinline__ uint32_t swz(uint32_t off) { return off ^ ((off >> 3) & 0x70u); }

// ---------------------------------------------------------------------------
// Convert kernels: fp32 -> fp16 in pre-swizzled blob layout
// ---------------------------------------------------------------------------
__device__ __forceinline__ void cvt8_store(const float* xs, unsigned char* blobbase,
                                           unsigned m_in_half, unsigned k_in_chunk) {
    union { unsigned short s[8]; uint4 v; } h;
#pragma unroll
    for (int j = 0; j < 8; j++) h.s[j] = __half_as_ushort(__float2half_rn(xs[j]));
    unsigned off = (m_in_half << 7) | (k_in_chunk << 1);
    *(uint4*)(blobbase + swz(off)) = h.v;
}

__global__ void __launch_bounds__(256) convX(const float* __restrict__ X) {
    unsigned idx = blockIdx.x * 256u + threadIdx.x;
    unsigned m  = idx >> 8;
    unsigned k0 = (idx & 255u) << 3;
    const float4* src = (const float4*)(X + (size_t)m * K_ + k0);
    float4 v0 = src[0], v1 = src[1];
    float xs[8] = {v0.x, v0.y, v0.z, v0.w, v1.x, v1.y, v1.z, v1.w};
    size_t blob = ((size_t)(m >> 7) * NKC + (k0 >> 6)) * TILE_BYTES;
    cvt8_store(xs, g_X + blob, m & 127u, k0 & 63u);
}

__global__ void __launch_bounds__(256) convW(const float* __restrict__ W,
                                             const float* __restrict__ A1,
                                             const float* __restrict__ B1,
                                             const float* __restrict__ A2,
                                             const float* __restrict__ B2) {
    unsigned idx = blockIdx.x * 256u + threadIdx.x;
    unsigned n  = idx >> 8;
    unsigned k0 = (idx & 255u) << 3;
    const float4* src = (const float4*)(W + (size_t)n * K_ + k0);
    float4 v0 = src[0], v1 = src[1];
    float xs[8] = {v0.x, v0.y, v0.z, v0.w, v1.x, v1.y, v1.z, v1.w};
    if (n >= D_) {
        const float* A;
        const float* Brow;
        if (n < 2 * D_) { A = A1; Brow = B1 + (size_t)(n - D_) * R_; }
        else            { A = A2; Brow = B2 + (size_t)(n - 2 * D_) * R_; }
#pragma unroll
        for (int r = 0; r < R_; r++) {
            float bv = Brow[r];
            const float* Ar = A + (size_t)r * K_ + k0;
#pragma unroll
            for (int j = 0; j < 8; j++) xs[j] = fmaf(bv, Ar[j], xs[j]);
        }
    }
    size_t blob = ((size_t)(n >> 7) * NKC + (k0 >> 6)) * TILE_BYTES;
    cvt8_store(xs, g_W + blob, n & 127u, k0 & 63u);
}

// ---------------------------------------------------------------------------
// GEMM: 128x256 CTA tile, 8 warps (2m x 4n), warp tile 64x64, BK=64,
// 4-stage cp.async pipeline, fp16 HMMA (m16n8k16), fp32 accumulate.
// ---------------------------------------------------------------------------
__device__ __forceinline__ void issue_chunk(uint32_t st, const unsigned char* ga,
                                            const unsigned char* gb0,
                                            const unsigned char* gb1, int tid) {
#pragma unroll
    for (int i = 0; i < 4; i++) {
        uint32_t off = (uint32_t)(i * 256 + tid) * 16u;
        CP_ASYNC16(st + off,          ga  + off);
        CP_ASYNC16(st + 16384u + off, gb0 + off);
        CP_ASYNC16(st + 32768u + off, gb1 + off);
    }
}

__global__ void __launch_bounds__(256, 1)
gemm_hmma(const float* __restrict__ bias, float* __restrict__ out) {
    extern __shared__ __align__(16) unsigned char smem_raw[];
    const uint32_t base = (smem_u32(smem_raw) + 1023u) & ~1023u;

    const int tid  = threadIdx.x;
    const int wid  = tid >> 5;
    const int lane = tid & 31;
    const int wm   = wid >> 2;          // 0..1  (64-row slab)
    const int wn   = wid & 3;           // 0..3  (64-col slab)

    const int bn = blockIdx.x;          // 0..23
    const int bm = blockIdx.y;          // 0..63

    const unsigned char* Ab  = g_X + (size_t)bm * NKC * TILE_BYTES;
    const unsigned char* Bb0 = g_W + (size_t)(bn * 2 + 0) * NKC * TILE_BYTES;
    const unsigned char* Bb1 = g_W + (size_t)(bn * 2 + 1) * NKC * TILE_BYTES;

    // Per-lane ldmatrix base byte offsets (pre-swizzle) within a tile image.
    const uint32_t a_base = (uint32_t)((wm * 64 + (lane & 15)) * 128 + ((lane >> 4) & 1) * 16);
    // B: warp's 64-col band lives entirely in one 128-row tile image
    const uint32_t b_tile = (wn >> 1) ? 16384u : 0u;
    const uint32_t b_base = (uint32_t)(((wn & 1) * 64 + (lane & 7) + ((lane >> 4) << 3)) * 128
                                       + ((lane >> 3) & 1) * 16);

    float acc[4][8][4];
#pragma unroll
    for (int i = 0; i < 4; i++)
#pragma unroll
        for (int j = 0; j < 8; j++)
#pragma unroll
            for (int q = 0; q < 4; q++) acc[i][j][q] = 0.0f;

    // Prologue: fill STAGES-1 stages
#pragma unroll
    for (int s = 0; s < STAGES - 1; s++) {
        issue_chunk(base + (uint32_t)s * STAGE_BYTES,
                    Ab  + (size_t)s * TILE_BYTES,
                    Bb0 + (size_t)s * TILE_BYTES,
                    Bb1 + (size_t)s * TILE_BYTES, tid);
        CP_COMMIT();
    }

    for (int kc = 0; kc < NKC; kc++) {
        CP_WAIT(STAGES - 2);
        __syncthreads();

        if (kc + STAGES - 1 < NKC) {
            issue_chunk(base + (uint32_t)((kc + STAGES - 1) % STAGES) * STAGE_BYTES,
                        Ab  + (size_t)(kc + STAGES - 1) * TILE_BYTES,
                        Bb0 + (size_t)(kc + STAGES - 1) * TILE_BYTES,
                        Bb1 + (size_t)(kc + STAGES - 1) * TILE_BYTES, tid);
        }
        CP_COMMIT();

        const uint32_t st = base + (uint32_t)(kc % STAGES) * STAGE_BYTES;
        const uint32_t As = st;
        const uint32_t Bs = st + 16384u + b_tile;

#pragma unroll
        for (int kk = 0; kk < 4; kk++) {
            const uint32_t kb = (uint32_t)kk * 32u;
            uint32_t a[16], b[16];
#pragma unroll
            for (int i = 0; i < 4; i++) {
                uint32_t o = swz(a_base + (uint32_t)i * 2048u + kb);
                LDSM_X4(a[4*i+0], a[4*i+1], a[4*i+2], a[4*i+3], As + o);
            }
#pragma unroll
            for (int g = 0; g < 4; g++) {
                uint32_t o = swz(b_base + (uint32_t)g * 2048u + kb);
                LDSM_X4(b[4*g+0], b[4*g+1], b[4*g+2], b[4*g+3], Bs + o);
            }
#pragma unroll
            for (int i = 0; i < 4; i++) {
#pragma unroll
                for (int j = 0; j < 8; j++) {
                    const int g = j >> 1, h = (j & 1) << 1;
                    MMA_F16(acc[i][j], a[4*i+0], a[4*i+1], a[4*i+2], a[4*i+3],
                            b[4*g+h], b[4*g+h+1]);
                }
            }
        }
    }

    // ---- epilogue: bias + store ----
    const int m0 = bm * 128 + wm * 64;
    const int n0 = bn * 256 + wn * 64;
    const int r  = lane >> 2;
    const int cp = (lane & 3) * 2;

#pragma unroll
    for (int j = 0; j < 8; j++) {
        const int n = n0 + j * 8 + cp;
        const float2 bv = *(const float2*)(bias + n);
#pragma unroll
        for (int i = 0; i < 4; i++) {
            const int row0 = m0 + i * 16 + r;
            float2 o0 = make_float2(acc[i][j][0] + bv.x, acc[i][j][1] + bv.y);
            float2 o1 = make_float2(acc[i][j][2] + bv.x, acc[i][j][3] + bv.y);
            *(float2*)(out + (size_t)row0 * NTOT + n)       = o0;
            *(float2*)(out + (size_t)(row0 + 8) * NTOT + n) = o1;
        }
    }
}

// ---------------------------------------------------------------------------
extern "C" void kernel_launch(void* const* d_in, const int* in_sizes, int n_in,
                              void* d_out, int out_size) {
    const float* x  = (const float*)d_in[0];
    const float* W  = (const float*)d_in[1];
    const float* b  = (const float*)d_in[2];
    const float* A1 = (const float*)d_in[3];
    const float* B1 = (const float*)d_in[4];
    const float* A2 = (const float*)d_in[5];
    const float* B2 = (const float*)d_in[6];
    float* out = (float*)d_out;

    convX<<<M_ * (K_ / 8) / 256, 256>>>(x);
    convW<<<NTOT * (K_ / 8) / 256, 256>>>(W, A1, B1, A2, B2);

    cudaFuncSetAttribute(gemm_hmma, cudaFuncAttributeMaxDynamicSharedMemorySize, SMEM_REQ);
    dim3 grid(NTOT / 256, M_ / 128);   // (24, 64)
    gemm_hmma<<<grid, 256, SMEM_REQ>>>(b, out);
}

// round 8
// speedup vs baseline: 8.0966x; 1.1739x over previous
#include <cuda_runtime.h>
#include <cuda_bf16.h>
#include <cuda_fp16.h>
#include <cstdint>

// ---------------------------------------------------------------------------
// Problem dims (fixed by the dataset)
// ---------------------------------------------------------------------------
#define D_     2048
#define K_     2048
#define NTOT   6144            // 3*D
#define M_     8192            // 4*2048
#define R_     8

#define KC        64           // k-elems per chunk (128B fp16 rows, SW128)
#define NKC       32           // K_/KC
#define MHALVES   64           // M_/128
#define NHALVES   48           // NTOT/128
#define TILE_BYTES  16384      // one 128x64 fp16 tile (SW128 image)
#define STAGES    3
#define STAGE_BYTES 32768      // A (16K) + B (16K)
#define SMEM_REQ  (STAGES * STAGE_BYTES + 1024)   // 99328 -> 2 CTAs/SM

// fp16 blobs, stored as byte-exact SW128 tile images:
// blob[half*32 + kc] = 16KB tile; byte (r, c) at sw128(r*128 + c*2)
__device__ __align__(128) unsigned char g_X[(size_t)MHALVES * NKC * TILE_BYTES]; // 32 MB
__device__ __align__(128) unsigned char g_W[(size_t)NHALVES * NKC * TILE_BYTES]; // 24 MB

// ---------------------------------------------------------------------------
// PTX helpers (baseline sm_80/90 features only)
// ---------------------------------------------------------------------------
__device__ __forceinline__ uint32_t smem_u32(const void* p) {
    uint32_t a;
    asm("{ .reg .u64 t; cvta.to.shared.u64 t, %1; cvt.u32.u64 %0, t; }" : "=r"(a) : "l"(p));
    return a;
}
#define CP_ASYNC16(s, g) \
    asm volatile("cp.async.cg.shared.global [%0], [%1], 16;" :: "r"(s), "l"(g) : "memory")
#define CP_COMMIT() asm volatile("cp.async.commit_group;" ::: "memory")
#define CP_WAIT(n)  asm volatile("cp.async.wait_group %0;" :: "n"(n) : "memory")

#define LDSM_X4(r0, r1, r2, r3, a) \
    asm volatile("ldmatrix.sync.aligned.m8n8.x4.shared.b16 {%0,%1,%2,%3}, [%4];" \
                 : "=r"(r0), "=r"(r1), "=r"(r2), "=r"(r3) : "r"(a))

#define MMA_F16(d, a0, a1, a2, a3, b0, b1) \
    asm volatile("mma.sync.aligned.m16n8k16.row.col.f32.f16.f16.f32 " \
                 "{%0,%1,%2,%3}, {%4,%5,%6,%7}, {%8,%9}, {%0,%1,%2,%3};" \
                 : "+f"((d)[0]), "+f"((d)[1]), "+f"((d)[2]), "+f"((d)[3]) \
                 : "r"(a0), "r"(a1), "r"(a2), "r"(a3), "r"(b0), "r"(b1))

__device__ __forceinline__ uint32_t swz(uint32_t off) { return off ^ ((off >> 3) & 0x70u); }

// ---------------------------------------------------------------------------
// Convert kernels: fp32 -> fp16 in pre-swizzled blob layout
// ---------------------------------------------------------------------------
__device__ __forceinline__ void cvt8_store(const float* xs, unsigned char* blobbase,
                                           unsigned m_in_half, unsigned k_in_chunk) {
    union { unsigned short s[8]; uint4 v; } h;
#pragma unroll
    for (int j = 0; j < 8; j++) h.s[j] = __half_as_ushort(__float2half_rn(xs[j]));
    unsigned off = (m_in_half << 7) | (k_in_chunk << 1);
    *(uint4*)(blobbase + swz(off)) = h.v;
}

__global__ void __launch_bounds__(256) convX(const float* __restrict__ X) {
    unsigned idx = blockIdx.x * 256u + threadIdx.x;
    unsigned m  = idx >> 8;
    unsigned k0 = (idx & 255u) << 3;
    const float4* src = (const float4*)(X + (size_t)m * K_ + k0);
    float4 v0 = src[0], v1 = src[1];
    float xs[8] = {v0.x, v0.y, v0.z, v0.w, v1.x, v1.y, v1.z, v1.w};
    size_t blob = ((size_t)(m >> 7) * NKC + (k0 >> 6)) * TILE_BYTES;
    cvt8_store(xs, g_X + blob, m & 127u, k0 & 63u);
}

__global__ void __launch_bounds__(256) convW(const float* __restrict__ W,
                                             const float* __restrict__ A1,
                                             const float* __restrict__ B1,
                                             const float* __restrict__ A2,
                                             const float* __restrict__ B2) {
    unsigned idx = blockIdx.x * 256u + threadIdx.x;
    unsigned n  = idx >> 8;
    unsigned k0 = (idx & 255u) << 3;
    const float4* src = (const float4*)(W + (size_t)n * K_ + k0);
    float4 v0 = src[0], v1 = src[1];
    float xs[8] = {v0.x, v0.y, v0.z, v0.w, v1.x, v1.y, v1.z, v1.w};
    if (n >= D_) {
        const float* A;
        const float* Brow;
        if (n < 2 * D_) { A = A1; Brow = B1 + (size_t)(n - D_) * R_; }
        else            { A = A2; Brow = B2 + (size_t)(n - 2 * D_) * R_; }
#pragma unroll
        for (int r = 0; r < R_; r++) {
            float bv = Brow[r];
            const float* Ar = A + (size_t)r * K_ + k0;
#pragma unroll
            for (int j = 0; j < 8; j++) xs[j] = fmaf(bv, Ar[j], xs[j]);
        }
    }
    size_t blob = ((size_t)(n >> 7) * NKC + (k0 >> 6)) * TILE_BYTES;
    cvt8_store(xs, g_W + blob, n & 127u, k0 & 63u);
}

// ---------------------------------------------------------------------------
// GEMM: 128x128 CTA tile, 4 warps (2m x 2n), warp tile 64x64, BK=64,
// 3-stage cp.async pipeline, 2 CTAs/SM, fp16 HMMA (m16n8k16), fp32 accumulate.
// ---------------------------------------------------------------------------
__device__ __forceinline__ void issue_chunk(uint32_t st, const unsigned char* ga,
                                            const unsigned char* gb, int tid) {
#pragma unroll
    for (int i = 0; i < 8; i++) {
        uint32_t off = (uint32_t)(i * 128 + tid) * 16u;
        CP_ASYNC16(st + off,          ga + off);
        CP_ASYNC16(st + 16384u + off, gb + off);
    }
}

__global__ void __launch_bounds__(128, 2)
gemm_hmma(const float* __restrict__ bias, float* __restrict__ out) {
    extern __shared__ __align__(16) unsigned char smem_raw[];
    const uint32_t base = (smem_u32(smem_raw) + 1023u) & ~1023u;

    const int tid  = threadIdx.x;
    const int wid  = tid >> 5;
    const int lane = tid & 31;
    const int wm   = wid >> 1;          // 0..1  (64-row slab)
    const int wn   = wid & 1;           // 0..1  (64-col slab)

    const int bn = blockIdx.x;          // 0..47
    const int bm = blockIdx.y;          // 0..63

    const unsigned char* Ab = g_X + (size_t)bm * NKC * TILE_BYTES;
    const unsigned char* Bb = g_W + (size_t)bn * NKC * TILE_BYTES;

    // Per-lane ldmatrix base byte offsets (pre-swizzle) within a tile image.
    const uint32_t a_base = (uint32_t)((wm * 64 + (lane & 15)) * 128 + ((lane >> 4) & 1) * 16);
    const uint32_t b_base = (uint32_t)((wn * 64 + (lane & 7) + ((lane >> 4) << 3)) * 128
                                       + ((lane >> 3) & 1) * 16);

    float acc[4][8][4];
#pragma unroll
    for (int i = 0; i < 4; i++)
#pragma unroll
        for (int j = 0; j < 8; j++)
#pragma unroll
            for (int q = 0; q < 4; q++) acc[i][j][q] = 0.0f;

    // Prologue: fill STAGES-1 stages
#pragma unroll
    for (int s = 0; s < STAGES - 1; s++) {
        issue_chunk(base + (uint32_t)s * STAGE_BYTES,
                    Ab + (size_t)s * TILE_BYTES,
                    Bb + (size_t)s * TILE_BYTES, tid);
        CP_COMMIT();
    }

    for (int kc = 0; kc < NKC; kc++) {
        CP_WAIT(STAGES - 2);
        __syncthreads();

        if (kc + STAGES - 1 < NKC) {
            issue_chunk(base + (uint32_t)((kc + STAGES - 1) % STAGES) * STAGE_BYTES,
                        Ab + (size_t)(kc + STAGES - 1) * TILE_BYTES,
                        Bb + (size_t)(kc + STAGES - 1) * TILE_BYTES, tid);
        }
        CP_COMMIT();

        const uint32_t st = base + (uint32_t)(kc % STAGES) * STAGE_BYTES;
        const uint32_t As = st;
        const uint32_t Bs = st + 16384u;

#pragma unroll
        for (int kk = 0; kk < 4; kk++) {
            const uint32_t kb = (uint32_t)kk * 32u;
            uint32_t a[16], b[16];
#pragma unroll
            for (int i = 0; i < 4; i++) {
                uint32_t o = swz(a_base + (uint32_t)i * 2048u + kb);
                LDSM_X4(a[4*i+0], a[4*i+1], a[4*i+2], a[4*i+3], As + o);
            }
#pragma unroll
            for (int g = 0; g < 4; g++) {
                uint32_t o = swz(b_base + (uint32_t)g * 2048u + kb);
                LDSM_X4(b[4*g+0], b[4*g+1], b[4*g+2], b[4*g+3], Bs + o);
            }
#pragma unroll
            for (int i = 0; i < 4; i++) {
#pragma unroll
                for (int j = 0; j < 8; j++) {
                    const int g = j >> 1, h = (j & 1) << 1;
                    MMA_F16(acc[i][j], a[4*i+0], a[4*i+1], a[4*i+2], a[4*i+3],
                            b[4*g+h], b[4*g+h+1]);
                }
            }
        }
    }

    // ---- epilogue: bias + store ----
    const int m0 = bm * 128 + wm * 64;
    const int n0 = bn * 128 + wn * 64;
    const int r  = lane >> 2;
    const int cp = (lane & 3) * 2;

#pragma unroll
    for (int j = 0; j < 8; j++) {
        const int n = n0 + j * 8 + cp;
        const float2 bv = *(const float2*)(bias + n);
#pragma unroll
        for (int i = 0; i < 4; i++) {
            const int row0 = m0 + i * 16 + r;
            float2 o0 = make_float2(acc[i][j][0] + bv.x, acc[i][j][1] + bv.y);
            float2 o1 = make_float2(acc[i][j][2] + bv.x, acc[i][j][3] + bv.y);
            *(float2*)(out + (size_t)row0 * NTOT + n)       = o0;
            *(float2*)(out + (size_t)(row0 + 8) * NTOT + n) = o1;
        }
    }
}

// ---------------------------------------------------------------------------
extern "C" void kernel_launch(void* const* d_in, const int* in_sizes, int n_in,
                              void* d_out, int out_size) {
    const float* x  = (const float*)d_in[0];
    const float* W  = (const float*)d_in[1];
    const float* b  = (const float*)d_in[2];
    const float* A1 = (const float*)d_in[3];
    const float* B1 = (const float*)d_in[4];
    const float* A2 = (const float*)d_in[5];
    const float* B2 = (const float*)d_in[6];
    float* out = (float*)d_out;

    convX<<<M_ * (K_ / 8) / 256, 256>>>(x);
    convW<<<NTOT * (K_ / 8) / 256, 256>>>(W, A1, B1, A2, B2);

    cudaFuncSetAttribute(gemm_hmma, cudaFuncAttributeMaxDynamicSharedMemorySize, SMEM_REQ);
    dim3 grid(NTOT / 128, M_ / 128);   // (48, 64)
    gemm_hmma<<<grid, 128, SMEM_REQ>>>(b, out);
}